// round 8
// baseline (speedup 1.0000x reference)
#include <cuda_runtime.h>
#include <cuda_fp16.h>
#include <cstdint>

// Problem constants
static const int E   = 8;
static const int HID = 2048;
static const int ITR = 1408;
static const int MPE = 1024;

// GEMM tiling (fp16 operands)
static const int BM  = 128;   // M rows per CTA
static const int BNR = 128;   // B-tile rows per CTA (MODE0: 64 out cols x {gate,up})
static const int BK  = 64;    // K halves per stage (= 128B row)
static const int NT  = 256;   // 8 warps -> no 128-reg cap, no spills
static const int SST = 36;    // smem row stride in words (32 data + 4 pad): conflict-free frags
static const int AST = BM * SST;    // words / A stage
static const int BST = BNR * SST;   // words / B stage
static const int NSTAGE = 3;
static const int SMEM_BYTES = NSTAGE * (AST + BST) * 4;  // 110592

// Packed (pre-scaled, fp16-rounded) operands + intermediate
__device__ __half g_w1[(size_t)E * 2 * ITR * HID];  // rows gate/up interleaved
__device__ __half g_w2[(size_t)E * HID * ITR];
__device__ __half g_a1[(size_t)E * MPE * HID];
__device__ __half g_dn[(size_t)E * MPE * ITR];      // silu(gate)*up, fp16

__device__ __forceinline__ uint32_t s2u(const void* p) {
    uint32_t a;
    asm("{ .reg .u64 t; cvta.to.shared.u64 t, %1; cvt.u32.u64 %0, t; }" : "=r"(a) : "l"(p));
    return a;
}
__device__ __forceinline__ void cp16(uint32_t dst, const void* src) {
    asm volatile("cp.async.cg.shared.global [%0], [%1], 16;" :: "r"(dst), "l"(src) : "memory");
}
__device__ __forceinline__ void mma16(float* c, const uint32_t* a, const uint32_t* b) {
    asm volatile(
        "mma.sync.aligned.m16n8k16.row.col.f32.f16.f16.f32 "
        "{%0,%1,%2,%3}, {%4,%5,%6,%7}, {%8,%9}, {%0,%1,%2,%3};\n"
        : "+f"(c[0]), "+f"(c[1]), "+f"(c[2]), "+f"(c[3])
        : "r"(a[0]), "r"(a[1]), "r"(a[2]), "r"(a[3]), "r"(b[0]), "r"(b[1]));
}

// ---------------- pack: dequant-scale + fp16-round + layout ----------------
__global__ void __launch_bounds__(256)
pack_all(const float* __restrict__ hs, const float* __restrict__ w1,
         const float* __restrict__ s1, const float* __restrict__ w2,
         const float* __restrict__ s2) {
    const size_t N1 = (size_t)E * 2 * ITR * (HID / 4);   // w1 float4 groups
    const size_t N2 = (size_t)E * HID * (ITR / 4);       // w2
    const size_t N3 = (size_t)E * MPE * (HID / 4);       // hs
    const size_t total = N1 + N2 + N3;
    size_t i = (size_t)blockIdx.x * blockDim.x + threadIdx.x;
    const size_t step = (size_t)gridDim.x * blockDim.x;
    for (; i < total; i += step) {
        if (i < N1) {
            const size_t f = i;
            const int kf = (int)(f % (HID / 4));
            const size_t row = f / (HID / 4);
            const int e = (int)(row / (2 * ITR));
            const int j = (int)(row % (2 * ITR));
            const int wr = (j & 1) ? (ITR + (j >> 1)) : (j >> 1);
            const float s = s1[((size_t)e * (2 * ITR / 128) + (wr >> 7)) * (HID / 128) + (kf >> 5)];
            float4 v = ((const float4*)w1)[((size_t)e * 2 * ITR + wr) * (HID / 4) + kf];
            ((__half2*)g_w1)[2 * f]     = __floats2half2_rn(v.x * s, v.y * s);
            ((__half2*)g_w1)[2 * f + 1] = __floats2half2_rn(v.z * s, v.w * s);
        } else if (i < N1 + N2) {
            const size_t f = i - N1;
            const int kf = (int)(f % (ITR / 4));
            const size_t row = f / (ITR / 4);
            const int e = (int)(row / HID);
            const int n = (int)(row % HID);
            const float s = s2[((size_t)e * (HID / 128) + (n >> 7)) * (ITR / 128) + (kf >> 5)];
            float4 v = ((const float4*)w2)[f];
            ((__half2*)g_w2)[2 * f]     = __floats2half2_rn(v.x * s, v.y * s);
            ((__half2*)g_w2)[2 * f + 1] = __floats2half2_rn(v.z * s, v.w * s);
        } else {
            const size_t f = i - N1 - N2;
            float4 v = ((const float4*)hs)[f];
            ((__half2*)g_a1)[2 * f]     = __floats2half2_rn(v.x, v.y);
            ((__half2*)g_a1)[2 * f + 1] = __floats2half2_rn(v.z, v.w);
        }
    }
}

// ---------------- fused GEMM (fp16 mma, fp32 accumulate) ----------------
// MODE 0: gate_up (K=2048) + silu*up -> g_dn.  B rows interleaved gate/up.
// MODE 1: down    (K=1408) -> Out (fp32).
template <int MODE>
__global__ void __launch_bounds__(NT, 1)
moe_gemm(float* __restrict__ Out) {
    constexpr int K  = (MODE == 0) ? HID : ITR;          // in halves
    constexpr int KT = K / BK;                           // 32 / 22
    constexpr int NWROWS = (MODE == 0) ? 2 * ITR : HID;

    extern __shared__ float sm[];
    const uint32_t sb = s2u(sm);
    const int tid = threadIdx.x, wid = tid >> 5, lane = tid & 31;
    const int g = lane >> 2, tg = lane & 3;
    const int e = blockIdx.z, m0 = blockIdx.y * BM, nb = blockIdx.x;

    const __half* Ag = ((MODE == 0) ? g_a1 : g_dn) + ((size_t)e * MPE + m0) * K;
    const __half* Bg = ((MODE == 0) ? g_w1 : g_w2) + ((size_t)e * NWROWS + (size_t)nb * BNR) * K;

    // cp.async: 16B chunks (8 halves); 8 chunks per 64-half row; 1024 chunks each of A/B
    auto issue = [&](int t) {
        const int buf = t % NSTAGE;
        const int k0 = t * BK;
        const uint32_t abase = sb + (uint32_t)(buf * (AST + BST)) * 4;
        const uint32_t bbase = abase + (uint32_t)AST * 4;
        #pragma unroll
        for (int i = 0; i < 4; i++) {                // A: 128 rows x 8 chunks
            int ci = tid + i * NT;
            int r = ci >> 3, c = ci & 7;
            cp16(abase + (uint32_t)r * (SST * 4) + c * 16, Ag + (size_t)r * K + k0 + c * 8);
        }
        #pragma unroll
        for (int i = 0; i < 4; i++) {                // B: 128 rows x 8 chunks
            int ci = tid + i * NT;
            int r = ci >> 3, c = ci & 7;
            cp16(bbase + (uint32_t)r * (SST * 4) + c * 16, Bg + (size_t)r * K + k0 + c * 8);
        }
    };

    float acc[4][4][4];
    #pragma unroll
    for (int a = 0; a < 4; a++)
        #pragma unroll
        for (int b = 0; b < 4; b++)
            #pragma unroll
            for (int c = 0; c < 4; c++) acc[a][b][c] = 0.f;

    const int wm = (wid >> 2) * 64;   // warp m-offset (0/64)
    const int wn = (wid & 3) * 32;    // warp n-offset in B rows (0/32/64/96)

    auto compute = [&](int buf) {
        const uint32_t* As = (const uint32_t*)sm + buf * (AST + BST);
        const uint32_t* Bs = As + AST;
        #pragma unroll
        for (int ks = 0; ks < 4; ks++) {             // k16 steps (8 words each)
            uint32_t af[4][4], bf[4][2];
            #pragma unroll
            for (int mi = 0; mi < 4; mi++) {
                const uint32_t* p0 = As + (wm + mi * 16 + g) * SST + ks * 8 + tg;
                const uint32_t* p1 = p0 + 8 * SST;
                af[mi][0] = p0[0]; af[mi][1] = p1[0]; af[mi][2] = p0[4]; af[mi][3] = p1[4];
            }
            #pragma unroll
            for (int ni = 0; ni < 4; ni++) {
                const uint32_t* p = Bs + (wn + ni * 8 + g) * SST + ks * 8 + tg;
                bf[ni][0] = p[0]; bf[ni][1] = p[4];
            }
            #pragma unroll
            for (int mi = 0; mi < 4; mi++)
                #pragma unroll
                for (int ni = 0; ni < 4; ni++)
                    mma16(acc[mi][ni], af[mi], bf[ni]);
        }
    };

    // ---- 3-stage pipeline: one tile always in flight during compute ----
    issue(0);
    asm volatile("cp.async.commit_group;" ::: "memory");
    issue(1);
    asm volatile("cp.async.commit_group;" ::: "memory");
    for (int t = 0; t < KT; t++) {
        asm volatile("cp.async.wait_group 1;" ::: "memory");
        __syncthreads();
        if (t + 2 < KT) issue(t + 2);
        asm volatile("cp.async.commit_group;" ::: "memory");
        compute(t % NSTAGE);
    }

    // ---- epilogue ----
    if (MODE == 0) {
        // c0/c1 = (gate, up) of one out-col, rows g / g+8 via c2/c3
        const int ncol = nb * (BNR / 2) + (wn >> 1) + tg;   // + ni*4
        __half* D = g_dn + ((size_t)e * MPE + m0 + wm + g) * ITR + ncol;
        #pragma unroll
        for (int mi = 0; mi < 4; mi++) {
            __half* Dr0 = D + (size_t)(mi * 16) * ITR;
            __half* Dr1 = Dr0 + (size_t)8 * ITR;
            #pragma unroll
            for (int ni = 0; ni < 4; ni++) {
                float g0 = acc[mi][ni][0], u0 = acc[mi][ni][1];
                float g1 = acc[mi][ni][2], u1 = acc[mi][ni][3];
                Dr0[ni * 4] = __float2half_rn((g0 / (1.f + __expf(-g0))) * u0);
                Dr1[ni * 4] = __float2half_rn((g1 / (1.f + __expf(-g1))) * u1);
            }
        }
    } else {
        const int ncol = nb * BNR + wn + 2 * tg;            // + ni*8
        float* D = Out + ((size_t)e * MPE + m0 + wm + g) * HID + ncol;
        #pragma unroll
        for (int mi = 0; mi < 4; mi++) {
            float* Dr0 = D + (size_t)(mi * 16) * HID;
            float* Dr1 = Dr0 + (size_t)8 * HID;
            #pragma unroll
            for (int ni = 0; ni < 4; ni++) {
                float2 o0 = {acc[mi][ni][0], acc[mi][ni][1]};
                float2 o1 = {acc[mi][ni][2], acc[mi][ni][3]};
                *(float2*)(Dr0 + ni * 8) = o0;
                *(float2*)(Dr1 + ni * 8) = o1;
            }
        }
    }
}

extern "C" void kernel_launch(void* const* d_in, const int* in_sizes, int n_in,
                              void* d_out, int out_size) {
    const float* hs = (const float*)d_in[0];
    // d_in[1] = tokens_per_expert (uniform 1024/expert; matches reference reshape)
    const float* w1 = (const float*)d_in[2];
    const float* s1 = (const float*)d_in[3];
    const float* w2 = (const float*)d_in[4];
    const float* s2 = (const float*)d_in[5];
    float* out = (float*)d_out;

    cudaFuncSetAttribute(moe_gemm<0>, cudaFuncAttributeMaxDynamicSharedMemorySize, SMEM_BYTES);
    cudaFuncSetAttribute(moe_gemm<1>, cudaFuncAttributeMaxDynamicSharedMemorySize, SMEM_BYTES);

    pack_all<<<4096, 256>>>(hs, w1, s1, w2, s2);
    // GEMM1 + silu*up: grid (2816/128, 8, 8) = (22, 8, 8)
    moe_gemm<0><<<dim3(2 * ITR / BNR, MPE / BM, E), NT, SMEM_BYTES>>>(nullptr);
    // GEMM2: grid (2048/128, 8, 8) = (16, 8, 8)
    moe_gemm<1><<<dim3(HID / BNR, MPE / BM, E), NT, SMEM_BYTES>>>(out);
}